// round 13
// baseline (speedup 1.0000x reference)
#include <cuda_runtime.h>
#include <cstdint>

#define Tn     2048
#define Dn     512
#define Hn     512
#define HDn    256
#define NTAGS  20
#define STARTT 18
#define ENDT   19
#define NEGV   (-10000.0f)

#define CSIZE    16    // CTAs per direction (one nonportable cluster)
#define RTHREADS 512

// ---------------- scratch (static device memory; no allocations) ----------------
__device__ __align__(16) float g_xg[2][Tn * 1024];     // per-dir gate preactivations
__device__ __align__(16) float g_x1[Tn * Hn];          // layer0 output (concat f|b)
__device__ __align__(16) float g_x2[Tn * Hn];          // layer1 output
__device__ __align__(16) float g_feats[Tn * NTAGS];
__device__ int g_tflags[2][2][16];                     // [layer][dir][mtile] n-block arrivals

// ---------------- PTX helpers ----------------
__device__ __forceinline__ uint32_t smem_u32(const void* p) {
    return (uint32_t)__cvta_generic_to_shared(p);
}

// remote (cluster) 8-byte store: value+tag in one word, no fence needed
__device__ __forceinline__ void st_cluster_u64(uint32_t laddr, uint32_t rank,
                                               unsigned long long v) {
    asm volatile("{\n\t"
        ".reg .b32 ra;\n\t"
        "mapa.shared::cluster.u32 ra, %0, %1;\n\t"
        "st.shared::cluster.u64 [ra], %2;\n\t"
        "}" :: "r"(laddr), "r"(rank), "l"(v) : "memory");
}

__device__ __forceinline__ void fma2(unsigned long long& acc,
                                     unsigned long long a, unsigned long long b) {
    asm("fma.rn.f32x2 %0, %1, %2, %0;" : "+l"(acc) : "l"(a), "l"(b));
}

__device__ __forceinline__ unsigned long long pk2(float lo, float hi) {
    unsigned long long r;
    asm("mov.b64 %0, {%1, %2};" : "=l"(r) : "f"(lo), "f"(hi));
    return r;
}

__device__ __forceinline__ unsigned long long pk2u(uint32_t lo, uint32_t hi) {
    unsigned long long r;
    asm("mov.b64 %0, {%1, %2};" : "=l"(r) : "r"(lo), "r"(hi));
    return r;
}

// single-instruction MUFU.TANH (sm_75+); sigmoid via tanh identity
__device__ __forceinline__ float tanh_apx(float x) {
    float r;
    asm("tanh.approx.f32 %0, %1;" : "=f"(r) : "f"(x));
    return r;
}
__device__ __forceinline__ float sig_apx(float x) {
    return fmaf(0.5f, tanh_apx(0.5f * x), 0.5f);
}

__global__ void zero_flags_kernel() {
    int* p = &g_tflags[0][0][0];
    if (threadIdx.x < 64) p[threadIdx.x] = 0;
}

// ---------------- GEMM: XG[dir] = X @ W^T + (bih + bhh), with tile flags ------
__global__ __launch_bounds__(256)
void gemm_kernel(int layer,
                 const float* __restrict__ A,
                 const int* __restrict__ sent, const float* __restrict__ emb,
                 const float* __restrict__ W0, const float* __restrict__ W1,
                 const float* __restrict__ bi0, const float* __restrict__ bh0,
                 const float* __restrict__ bi1, const float* __restrict__ bh1) {
    const int K = 512;
    int dir = blockIdx.y;
    int mi = blockIdx.z;
    int mt = (mi & 1) ? (15 - (mi >> 1)) : (mi >> 1);
    const float* B  = dir ? W1 : W0;
    const float* bi = dir ? bi1 : bi0;
    const float* bh = dir ? bh1 : bh0;
    float* C = g_xg[dir];

    __shared__ float As[8][128];
    __shared__ float Bs[8][128];

    int tid = threadIdx.x;
    int bm = mt * 128;
    int bn = blockIdx.x * 128;
    int lr = tid >> 1;
    int lc = (tid & 1) * 4;
    int tx = tid & 15;
    int ty = tid >> 4;

    unsigned long long acc[8][4];
#pragma unroll
    for (int i = 0; i < 8; i++)
#pragma unroll
        for (int j = 0; j < 4; j++) acc[i][j] = 0ull;

    long arow = bm + lr;
    const float* Asrc = A;
    if (sent) { arow = __ldg(&sent[bm + lr]); Asrc = emb; }
    const float* Ap = Asrc + arow * K + lc;
    const float* Bp = B + (long)(bn + lr) * K + lc;

    for (int k0 = 0; k0 < K; k0 += 8) {
        float4 av = *(const float4*)(Ap + k0);
        float4 bv = *(const float4*)(Bp + k0);
        As[lc + 0][lr] = av.x; As[lc + 1][lr] = av.y;
        As[lc + 2][lr] = av.z; As[lc + 3][lr] = av.w;
        Bs[lc + 0][lr] = bv.x; Bs[lc + 1][lr] = bv.y;
        Bs[lc + 2][lr] = bv.z; Bs[lc + 3][lr] = bv.w;
        __syncthreads();
#pragma unroll
        for (int kk = 0; kk < 8; kk++) {
            float4 a0 = *(const float4*)&As[kk][ty * 4];
            float4 a1 = *(const float4*)&As[kk][64 + ty * 4];
            float4 b0 = *(const float4*)&Bs[kk][tx * 4];
            float4 b1 = *(const float4*)&Bs[kk][64 + tx * 4];
            float a[8] = {a0.x, a0.y, a0.z, a0.w, a1.x, a1.y, a1.z, a1.w};
            unsigned long long pb[4];
            pb[0] = pk2(b0.x, b0.y); pb[1] = pk2(b0.z, b0.w);
            pb[2] = pk2(b1.x, b1.y); pb[3] = pk2(b1.z, b1.w);
#pragma unroll
            for (int i = 0; i < 8; i++) {
                unsigned long long pa = pk2(a[i], a[i]);
#pragma unroll
                for (int j = 0; j < 4; j++)
                    fma2(acc[i][j], pa, pb[j]);
            }
        }
        __syncthreads();
    }

#pragma unroll
    for (int i = 0; i < 8; i++) {
        int m = bm + ((i < 4) ? (ty * 4 + i) : (64 + ty * 4 + (i - 4)));
#pragma unroll
        for (int j = 0; j < 8; j++) {
            int n = bn + ((j < 4) ? (tx * 4 + j) : (64 + tx * 4 + (j - 4)));
            unsigned long long p = acc[i][j >> 1];
            float v = __uint_as_float((j & 1) ? (uint32_t)(p >> 32) : (uint32_t)p);
            C[(long)m * 1024 + n] = v + __ldg(&bi[n]) + __ldg(&bh[n]);
        }
    }

    // publish tile completion
    __threadfence();
    __syncthreads();
    if (tid == 0) atomicAdd(&g_tflags[layer][dir][mt], 1);
}

// ---------------- recurrence: cluster-of-16, tagged-data + watcher flag -------
// Grid: 32 CTAs (2 nonportable clusters of 16). CTA rank owns cells
// [rank*16, rank*16+16). Warp w owns all 4 gate rows of cell cbase+w.
// h travels as (value, step-tag) u64 words. Every warp consumes all 256 pairs,
// so warp 15 (top arbiter priority) acts as the CTA's WATCHER: it tight-spins
// on its own tag scan (== full arrival scan) and publishes a per-step flag.
// Warps 0-14 tight-spin on that single broadcast word (1 wavefront, no
// crossbar pressure) and then single-shot-load their guaranteed-valid pairs.
// No sleep jitter, ~16x less poll traffic than R12.
__global__ __launch_bounds__(RTHREADS, 1) __cluster_dims__(CSIZE, 1, 1)
void recur_kernel(int layer,
                  const float* __restrict__ Whh_f,
                  const float* __restrict__ Whh_b,
                  float* __restrict__ xnext) {
    __shared__ __align__(16) unsigned long long pairs[2][HDn];  // (h bits | tag<<32)
    __shared__ uint32_t stepflag[2];

    int dir = blockIdx.x / CSIZE;
    uint32_t rank;
    asm("mov.u32 %0, %%cluster_ctarank;" : "=r"(rank));
    int cbase = (int)rank * 16;

    int tid = threadIdx.x;
    int w = tid >> 5;                    // warp -> local cell index 0..15
    int lane = tid & 31;
    int mycell = cbase + w;

    // init tags + flags to invalid, then cluster-wide sync before remote stores
    (&pairs[0][0])[tid] = 0xFFFFFFFF00000000ull;     // 512 entries, 512 threads
    if (tid < 2) stepflag[tid] = 0xFFFFFFFFu;
    __syncthreads();
    asm volatile("barrier.cluster.arrive.aligned;" ::: "memory");
    asm volatile("barrier.cluster.wait.aligned;" ::: "memory");

    const float* Whh = dir ? Whh_b : Whh_f;
    const float* xg = g_xg[dir];

    // register-resident weights for gate g, columns {64k+2*lane, 64k+2*lane+1}
    unsigned long long wregs[4][4];
#pragma unroll
    for (int g = 0; g < 4; g++) {
        int grow = g * HDn + mycell;
#pragma unroll
        for (int k = 0; k < 4; k++)
            wregs[g][k] = *(const unsigned long long*)
                (Whh + (size_t)grow * HDn + 64 * k + 2 * lane);
    }

    int mygate = lane >> 3;                           // gate this lane group reduces to
    size_t xg_off = (size_t)mygate * HDn + mycell;

    uint32_t pbase = smem_u32(&pairs[0][0]);
    uint32_t pollb = pbase + lane * 16;               // + 512*k + pb*2048
    uint32_t dstoff = pbase + mycell * 8;             // this warp's h slot (buf 0)
    volatile uint32_t* vflag = (volatile uint32_t*)stepflag;

    float c = 0.f;                                    // identical in all lanes

    for (int s = 0; s < Tn; s++) {
        int t = dir ? (Tn - 1 - s) : s;

        // per-tile gate on GEMM progress (once per 128 steps)
        if ((s & 127) == 0) {
            if (tid == 0) {
                int mt = dir ? (15 - (s >> 7)) : (s >> 7);
                volatile int* f = &g_tflags[layer][dir][mt];
                while (*f < 8) { __nanosleep(200); }
                __threadfence();
            }
            __syncthreads();
        }

        float xgv = __ldg(&xg[(size_t)t * 1024 + xg_off]);

        float z = xgv;
        if (s > 0) {
            uint32_t want = (uint32_t)(s - 1);
            int pb = (s - 1) & 1;
            uint32_t b = pollb + pb * (HDn * 8);
            unsigned long long p0, p1, p2, p3, p4, p5, p6, p7;

            if (w == 15) {
                // WATCHER: tight spin on own tags (== full arrival scan)
                for (;;) {
                    asm volatile("ld.volatile.shared.v2.u64 {%0,%1}, [%2];"
                                 : "=l"(p0), "=l"(p1) : "r"(b));
                    asm volatile("ld.volatile.shared.v2.u64 {%0,%1}, [%2];"
                                 : "=l"(p2), "=l"(p3) : "r"(b + 512));
                    asm volatile("ld.volatile.shared.v2.u64 {%0,%1}, [%2];"
                                 : "=l"(p4), "=l"(p5) : "r"(b + 1024));
                    asm volatile("ld.volatile.shared.v2.u64 {%0,%1}, [%2];"
                                 : "=l"(p6), "=l"(p7) : "r"(b + 1536));
                    bool ok = ((uint32_t)(p0 >> 32) == want) & ((uint32_t)(p1 >> 32) == want) &
                              ((uint32_t)(p2 >> 32) == want) & ((uint32_t)(p3 >> 32) == want) &
                              ((uint32_t)(p4 >> 32) == want) & ((uint32_t)(p5 >> 32) == want) &
                              ((uint32_t)(p6 >> 32) == want) & ((uint32_t)(p7 >> 32) == want);
                    if (__all_sync(0xffffffffu, ok)) break;
                }
                if (lane == 0) vflag[pb] = want;
            } else {
                // CONSUMER: tight spin on the broadcast flag, then one-shot load
                while (vflag[pb] != want) { }
                asm volatile("ld.volatile.shared.v2.u64 {%0,%1}, [%2];"
                             : "=l"(p0), "=l"(p1) : "r"(b));
                asm volatile("ld.volatile.shared.v2.u64 {%0,%1}, [%2];"
                             : "=l"(p2), "=l"(p3) : "r"(b + 512));
                asm volatile("ld.volatile.shared.v2.u64 {%0,%1}, [%2];"
                             : "=l"(p4), "=l"(p5) : "r"(b + 1024));
                asm volatile("ld.volatile.shared.v2.u64 {%0,%1}, [%2];"
                             : "=l"(p6), "=l"(p7) : "r"(b + 1536));
            }

            // pack h pairs (adjacent columns 2l, 2l+1 within each group)
            unsigned long long hx[4];
            hx[0] = pk2u((uint32_t)p0, (uint32_t)p1);
            hx[1] = pk2u((uint32_t)p2, (uint32_t)p3);
            hx[2] = pk2u((uint32_t)p4, (uint32_t)p5);
            hx[3] = pk2u((uint32_t)p6, (uint32_t)p7);

            float srow[4];
#pragma unroll
            for (int g = 0; g < 4; g++) {
                unsigned long long a = 0ull;
                fma2(a, wregs[g][0], hx[0]);
                fma2(a, wregs[g][1], hx[1]);
                fma2(a, wregs[g][2], hx[2]);
                fma2(a, wregs[g][3], hx[3]);
                float lo = __uint_as_float((uint32_t)a);
                float hi = __uint_as_float((uint32_t)(a >> 32));
                srow[g] = lo + hi;
            }
            // split-butterfly: 6 shfl; gate g lands in lane group 8g
#pragma unroll
            for (int i = 0; i < 2; i++) {
                float send = (lane & 16) ? srow[i] : srow[i + 2];
                float recv = __shfl_xor_sync(0xffffffffu, send, 16);
                srow[i] = ((lane & 16) ? srow[i + 2] : srow[i]) + recv;
            }
            {
                float send = (lane & 8) ? srow[0] : srow[1];
                float recv = __shfl_xor_sync(0xffffffffu, send, 8);
                srow[0] = ((lane & 8) ? srow[1] : srow[0]) + recv;
            }
            srow[0] += __shfl_xor_sync(0xffffffffu, srow[0], 4);
            srow[0] += __shfl_xor_sync(0xffffffffu, srow[0], 2);
            srow[0] += __shfl_xor_sync(0xffffffffu, srow[0], 1);
            z += srow[0];
        }

        // collect the 4 gates (all lanes receive; all maintain c identically)
        float zi = __shfl_sync(0xffffffffu, z, 0);
        float zf = __shfl_sync(0xffffffffu, z, 8);
        float zg = __shfl_sync(0xffffffffu, z, 16);
        float zo = __shfl_sync(0xffffffffu, z, 24);

        float ig = sig_apx(zi);
        float fg = sig_apx(zf);
        float og = sig_apx(zo);
        c = fg * c + ig * tanh_apx(zg);
        float h = og * tanh_apx(c);

        // publish: lanes 0..15 each store (h | s<<32) to one cluster CTA
        unsigned long long pv = pk2u(__float_as_uint(h), (uint32_t)s);
        uint32_t dst = dstoff + (s & 1) * (HDn * 8);
        if (lane < CSIZE) st_cluster_u64(dst, (uint32_t)lane, pv);
        if (lane == 16)
            xnext[(size_t)t * Hn + dir * HDn + mycell] = h;
    }

    asm volatile("barrier.cluster.arrive.aligned;" ::: "memory");
    asm volatile("barrier.cluster.wait.aligned;" ::: "memory");
}

// ---------------- projection: feats = x2 @ W_out^T + b_out ----------------
__global__ void proj_kernel(const float* __restrict__ Wout,
                            const float* __restrict__ bout) {
    int t = blockIdx.x;
    __shared__ float xs[Hn];
    int tid = threadIdx.x;   // 160
    for (int i = tid; i < Hn; i += 160) xs[i] = g_x2[(long)t * Hn + i];
    __syncthreads();
    int tag = tid >> 3;      // 0..19
    int p = tid & 7;
    float sum = 0.f;
    const float* wr = Wout + (long)tag * Hn + p * 64;
    const float* xr = xs + p * 64;
#pragma unroll
    for (int i = 0; i < 64; i++) sum = fmaf(__ldg(&wr[i]), xr[i], sum);
    sum += __shfl_xor_sync(0xffffffffu, sum, 1);
    sum += __shfl_xor_sync(0xffffffffu, sum, 2);
    sum += __shfl_xor_sync(0xffffffffu, sum, 4);
    if (p == 0) g_feats[t * NTAGS + tag] = sum + __ldg(&bout[tag]);
}

// ---------------- Viterbi: one warp; feats preloaded into smem; tree argmax ---
#define VSMEM_BYTES (Tn * NTAGS * 4 + Tn * NTAGS)
__global__ void viterbi_kernel(const float* __restrict__ trans,
                               float* __restrict__ out, int out_size) {
    extern __shared__ unsigned char vsm[];
    float* fs = (float*)vsm;                          // [Tn][NTAGS]
    unsigned char* bp = vsm + Tn * NTAGS * 4;         // [Tn][NTAGS]

    int n = threadIdx.x;                              // 0..31
    for (int i = n; i < Tn * NTAGS; i += 32) fs[i] = __ldg(&g_feats[i]);

    bool act = (n < NTAGS);
    float tr[NTAGS];
#pragma unroll
    for (int p = 0; p < NTAGS; p++) tr[p] = act ? __ldg(&trans[n * NTAGS + p]) : 0.f;
    float trE = act ? __ldg(&trans[ENDT * NTAGS + n]) : 0.f;
    float v = act ? ((n == STARTT) ? 0.f : NEGV) : -1e30f;
    __syncwarp();

    for (int t = 0; t < Tn; t++) {
        float sc[NTAGS];
#pragma unroll
        for (int p = 0; p < NTAGS; p++)
            sc[p] = __shfl_sync(0xffffffffu, v, p) + tr[p];

        float mv[10]; int mi_[10];
#pragma unroll
        for (int i = 0; i < 10; i++) {
            bool left = sc[2 * i] >= sc[2 * i + 1];
            mv[i] = left ? sc[2 * i] : sc[2 * i + 1];
            mi_[i] = left ? 2 * i : 2 * i + 1;
        }
#pragma unroll
        for (int i = 0; i < 5; i++) {
            bool left = mv[2 * i] >= mv[2 * i + 1];
            mv[i] = left ? mv[2 * i] : mv[2 * i + 1];
            mi_[i] = left ? mi_[2 * i] : mi_[2 * i + 1];
        }
        {
            bool l0 = mv[0] >= mv[1];
            float v0 = l0 ? mv[0] : mv[1]; int i0 = l0 ? mi_[0] : mi_[1];
            bool l1 = mv[2] >= mv[3];
            float v1 = l1 ? mv[2] : mv[3]; int i1 = l1 ? mi_[2] : mi_[3];
            bool l2 = v0 >= v1;
            float v2 = l2 ? v0 : v1; int i2 = l2 ? i0 : i1;
            bool l3 = v2 >= mv[4];
            mv[0] = l3 ? v2 : mv[4]; mi_[0] = l3 ? i2 : mi_[4];
        }
        float feat = act ? fs[t * NTAGS + n] : 0.f;
        v = mv[0] + feat;
        if (act) bp[t * NTAGS + n] = (unsigned char)mi_[0];
    }

    float term = act ? (v + trE) : -1e30f;
    int idx = act ? n : 31;
#pragma unroll
    for (int off = 16; off; off >>= 1) {
        float ov = __shfl_xor_sync(0xffffffffu, term, off);
        int oi = __shfl_xor_sync(0xffffffffu, idx, off);
        if (ov > term || (ov == term && oi < idx)) { term = ov; idx = oi; }
    }
    __syncwarp();

    if (n == 0) {
        if (out_size > 0) out[0] = term;
        int tag = idx;
        for (int t = Tn - 1; t >= 0; t--) {
            if (1 + t < out_size) out[1 + t] = (float)tag;
            tag = bp[t * NTAGS + tag];
        }
        for (int i = Tn + 1; i < out_size; i++) out[i] = 0.f;
    }
}

// ---------------- launch ----------------
extern "C" void kernel_launch(void* const* d_in, const int* in_sizes, int n_in,
                              void* d_out, int out_size) {
    const int*   sent    = (const int*)d_in[0];
    const float* emb     = (const float*)d_in[1];
    const float* l0f_Wih = (const float*)d_in[2];
    const float* l0f_Whh = (const float*)d_in[3];
    const float* l0f_bih = (const float*)d_in[4];
    const float* l0f_bhh = (const float*)d_in[5];
    const float* l0b_Wih = (const float*)d_in[6];
    const float* l0b_Whh = (const float*)d_in[7];
    const float* l0b_bih = (const float*)d_in[8];
    const float* l0b_bhh = (const float*)d_in[9];
    const float* l1f_Wih = (const float*)d_in[10];
    const float* l1f_Whh = (const float*)d_in[11];
    const float* l1f_bih = (const float*)d_in[12];
    const float* l1f_bhh = (const float*)d_in[13];
    const float* l1b_Wih = (const float*)d_in[14];
    const float* l1b_Whh = (const float*)d_in[15];
    const float* l1b_bih = (const float*)d_in[16];
    const float* l1b_bhh = (const float*)d_in[17];
    const float* W_out   = (const float*)d_in[18];
    const float* b_out   = (const float*)d_in[19];
    const float* trans   = (const float*)d_in[20];
    float* out = (float*)d_out;

    static float* s_x1 = nullptr;
    static float* s_x2 = nullptr;
    static cudaStream_t s1 = nullptr;
    static cudaEvent_t ev0 = nullptr, ev1 = nullptr, ev2 = nullptr;
    if (!s_x1) {
        cudaGetSymbolAddress((void**)&s_x1, g_x1);
        cudaGetSymbolAddress((void**)&s_x2, g_x2);
        cudaStreamCreateWithFlags(&s1, cudaStreamNonBlocking);
        cudaEventCreateWithFlags(&ev0, cudaEventDisableTiming);
        cudaEventCreateWithFlags(&ev1, cudaEventDisableTiming);
        cudaEventCreateWithFlags(&ev2, cudaEventDisableTiming);
        cudaFuncSetAttribute(viterbi_kernel,
                             cudaFuncAttributeMaxDynamicSharedMemorySize, VSMEM_BYTES);
        cudaFuncSetAttribute(recur_kernel,
                             cudaFuncAttributeNonPortableClusterSizeAllowed, 1);
    }

    dim3 ggrid(8, 2, 16);   // n-tile, dir, mi (interleaved m-tiles)

    // stream 0 (captured): zero flags, then recurrences
    zero_flags_kernel<<<1, 64>>>();
    cudaEventRecord(ev0, 0);
    cudaStreamWaitEvent(s1, ev0, 0);

    // GEMM0 on side stream, concurrent with recur0 (flag-gated per tile)
    gemm_kernel<<<ggrid, 256, 0, s1>>>(0, nullptr, sent, emb, l0f_Wih, l0b_Wih,
                                       l0f_bih, l0f_bhh, l0b_bih, l0b_bhh);
    recur_kernel<<<2 * CSIZE, RTHREADS>>>(0, l0f_Whh, l0b_Whh, s_x1);

    // GEMM1 must wait for x1 (recur0 done), then runs concurrent with recur1
    cudaEventRecord(ev1, 0);
    cudaStreamWaitEvent(s1, ev1, 0);
    gemm_kernel<<<ggrid, 256, 0, s1>>>(1, s_x1, nullptr, nullptr, l1f_Wih, l1b_Wih,
                                       l1f_bih, l1f_bhh, l1b_bih, l1b_bhh);
    cudaEventRecord(ev2, s1);

    recur_kernel<<<2 * CSIZE, RTHREADS>>>(1, l1f_Whh, l1b_Whh, s_x2);

    // join side stream back before epilogue
    cudaStreamWaitEvent(0, ev2, 0);
    proj_kernel<<<Tn, 160>>>(W_out, b_out);
    viterbi_kernel<<<1, 32, VSMEM_BYTES>>>(trans, out, out_size);
}

// round 14
// speedup vs baseline: 1.0271x; 1.0271x over previous
#include <cuda_runtime.h>
#include <cstdint>

#define Tn     2048
#define Dn     512
#define Hn     512
#define HDn    256
#define NTAGS  20
#define STARTT 18
#define ENDT   19
#define NEGV   (-10000.0f)

#define CSIZE    16    // CTAs per direction (one nonportable cluster)
#define RTHREADS 512

// ---------------- scratch (static device memory; no allocations) ----------------
__device__ __align__(16) float g_xg[2][Tn * 1024];     // per-dir gate preactivations
__device__ __align__(16) float g_x1[Tn * Hn];          // layer0 output (concat f|b)
__device__ __align__(16) float g_x2[Tn * Hn];          // layer1 output
__device__ __align__(16) float g_feats[Tn * NTAGS];
__device__ int g_tflags[2][2][16];                     // [layer][dir][mtile] n-block arrivals

// ---------------- PTX helpers ----------------
__device__ __forceinline__ uint32_t smem_u32(const void* p) {
    return (uint32_t)__cvta_generic_to_shared(p);
}

// remote (cluster) 8-byte store: value+tag in one word, no fence needed
__device__ __forceinline__ void st_cluster_u64(uint32_t laddr, uint32_t rank,
                                               unsigned long long v) {
    asm volatile("{\n\t"
        ".reg .b32 ra;\n\t"
        "mapa.shared::cluster.u32 ra, %0, %1;\n\t"
        "st.shared::cluster.u64 [ra], %2;\n\t"
        "}" :: "r"(laddr), "r"(rank), "l"(v) : "memory");
}

__device__ __forceinline__ void st_local_u64(uint32_t laddr, unsigned long long v) {
    asm volatile("st.volatile.shared.u64 [%0], %1;" :: "r"(laddr), "l"(v) : "memory");
}

__device__ __forceinline__ void fma2(unsigned long long& acc,
                                     unsigned long long a, unsigned long long b) {
    asm("fma.rn.f32x2 %0, %1, %2, %0;" : "+l"(acc) : "l"(a), "l"(b));
}

__device__ __forceinline__ unsigned long long pk2(float lo, float hi) {
    unsigned long long r;
    asm("mov.b64 %0, {%1, %2};" : "=l"(r) : "f"(lo), "f"(hi));
    return r;
}

__device__ __forceinline__ unsigned long long pk2u(uint32_t lo, uint32_t hi) {
    unsigned long long r;
    asm("mov.b64 %0, {%1, %2};" : "=l"(r) : "r"(lo), "r"(hi));
    return r;
}

// single-instruction MUFU.TANH (sm_75+); sigmoid via tanh identity
__device__ __forceinline__ float tanh_apx(float x) {
    float r;
    asm("tanh.approx.f32 %0, %1;" : "=f"(r) : "f"(x));
    return r;
}
__device__ __forceinline__ float sig_apx(float x) {
    return fmaf(0.5f, tanh_apx(0.5f * x), 0.5f);
}

__global__ void zero_flags_kernel() {
    int* p = &g_tflags[0][0][0];
    if (threadIdx.x < 64) p[threadIdx.x] = 0;
}

// ---------------- GEMM: XG[dir] = X @ W^T + (bih + bhh), with tile flags ------
__global__ __launch_bounds__(256)
void gemm_kernel(int layer,
                 const float* __restrict__ A,
                 const int* __restrict__ sent, const float* __restrict__ emb,
                 const float* __restrict__ W0, const float* __restrict__ W1,
                 const float* __restrict__ bi0, const float* __restrict__ bh0,
                 const float* __restrict__ bi1, const float* __restrict__ bh1) {
    const int K = 512;
    int dir = blockIdx.y;
    int mi = blockIdx.z;
    int mt = (mi & 1) ? (15 - (mi >> 1)) : (mi >> 1);
    const float* B  = dir ? W1 : W0;
    const float* bi = dir ? bi1 : bi0;
    const float* bh = dir ? bh1 : bh0;
    float* C = g_xg[dir];

    __shared__ float As[8][128];
    __shared__ float Bs[8][128];

    int tid = threadIdx.x;
    int bm = mt * 128;
    int bn = blockIdx.x * 128;
    int lr = tid >> 1;
    int lc = (tid & 1) * 4;
    int tx = tid & 15;
    int ty = tid >> 4;

    unsigned long long acc[8][4];
#pragma unroll
    for (int i = 0; i < 8; i++)
#pragma unroll
        for (int j = 0; j < 4; j++) acc[i][j] = 0ull;

    long arow = bm + lr;
    const float* Asrc = A;
    if (sent) { arow = __ldg(&sent[bm + lr]); Asrc = emb; }
    const float* Ap = Asrc + arow * K + lc;
    const float* Bp = B + (long)(bn + lr) * K + lc;

    for (int k0 = 0; k0 < K; k0 += 8) {
        float4 av = *(const float4*)(Ap + k0);
        float4 bv = *(const float4*)(Bp + k0);
        As[lc + 0][lr] = av.x; As[lc + 1][lr] = av.y;
        As[lc + 2][lr] = av.z; As[lc + 3][lr] = av.w;
        Bs[lc + 0][lr] = bv.x; Bs[lc + 1][lr] = bv.y;
        Bs[lc + 2][lr] = bv.z; Bs[lc + 3][lr] = bv.w;
        __syncthreads();
#pragma unroll
        for (int kk = 0; kk < 8; kk++) {
            float4 a0 = *(const float4*)&As[kk][ty * 4];
            float4 a1 = *(const float4*)&As[kk][64 + ty * 4];
            float4 b0 = *(const float4*)&Bs[kk][tx * 4];
            float4 b1 = *(const float4*)&Bs[kk][64 + tx * 4];
            float a[8] = {a0.x, a0.y, a0.z, a0.w, a1.x, a1.y, a1.z, a1.w};
            unsigned long long pb[4];
            pb[0] = pk2(b0.x, b0.y); pb[1] = pk2(b0.z, b0.w);
            pb[2] = pk2(b1.x, b1.y); pb[3] = pk2(b1.z, b1.w);
#pragma unroll
            for (int i = 0; i < 8; i++) {
                unsigned long long pa = pk2(a[i], a[i]);
#pragma unroll
                for (int j = 0; j < 4; j++)
                    fma2(acc[i][j], pa, pb[j]);
            }
        }
        __syncthreads();
    }

#pragma unroll
    for (int i = 0; i < 8; i++) {
        int m = bm + ((i < 4) ? (ty * 4 + i) : (64 + ty * 4 + (i - 4)));
#pragma unroll
        for (int j = 0; j < 8; j++) {
            int n = bn + ((j < 4) ? (tx * 4 + j) : (64 + tx * 4 + (j - 4)));
            unsigned long long p = acc[i][j >> 1];
            float v = __uint_as_float((j & 1) ? (uint32_t)(p >> 32) : (uint32_t)p);
            C[(long)m * 1024 + n] = v + __ldg(&bi[n]) + __ldg(&bh[n]);
        }
    }

    // publish tile completion
    __threadfence();
    __syncthreads();
    if (tid == 0) atomicAdd(&g_tflags[layer][dir][mt], 1);
}

// ---------------- recurrence: cluster-of-16, tagged-data, adaptive backoff ----
// Grid: 32 CTAs (2 nonportable clusters of 16). CTA rank owns cells
// [rank*16, rank*16+16). Warp w owns all 4 gate rows of cell cbase+w.
// h travels as (value, step-tag) u64 words; lane l consumes columns
// {64k+2l, 64k+2l+1}, polled with coalesced v2.u64 loads. Adaptive backoff:
// two fast polls (common case — no sleep-quantum cost), then 20ns sleeps.
// Producer's store to its own CTA is a plain local st.shared (no fabric hop).
__global__ __launch_bounds__(RTHREADS, 1) __cluster_dims__(CSIZE, 1, 1)
void recur_kernel(int layer,
                  const float* __restrict__ Whh_f,
                  const float* __restrict__ Whh_b,
                  float* __restrict__ xnext) {
    __shared__ __align__(16) unsigned long long pairs[2][HDn];  // (h bits | tag<<32)

    int dir = blockIdx.x / CSIZE;
    uint32_t rank;
    asm("mov.u32 %0, %%cluster_ctarank;" : "=r"(rank));
    int cbase = (int)rank * 16;

    int tid = threadIdx.x;
    int w = tid >> 5;                    // warp -> local cell index 0..15
    int lane = tid & 31;
    int mycell = cbase + w;

    // init tags to invalid, then cluster-wide sync before any remote store
    (&pairs[0][0])[tid] = 0xFFFFFFFF00000000ull;     // 512 entries, 512 threads
    __syncthreads();
    asm volatile("barrier.cluster.arrive.aligned;" ::: "memory");
    asm volatile("barrier.cluster.wait.aligned;" ::: "memory");

    const float* Whh = dir ? Whh_b : Whh_f;
    const float* xg = g_xg[dir];

    // register-resident weights for gate g, columns {64k+2*lane, 64k+2*lane+1}
    unsigned long long wregs[4][4];
#pragma unroll
    for (int g = 0; g < 4; g++) {
        int grow = g * HDn + mycell;
#pragma unroll
        for (int k = 0; k < 4; k++)
            wregs[g][k] = *(const unsigned long long*)
                (Whh + (size_t)grow * HDn + 64 * k + 2 * lane);
    }

    int mygate = lane >> 3;                           // gate this lane group reduces to
    size_t xg_off = (size_t)mygate * HDn + mycell;

    uint32_t pbase = smem_u32(&pairs[0][0]);
    uint32_t pollb = pbase + lane * 16;               // + 512*k + pb*2048
    uint32_t dstoff = pbase + mycell * 8;             // this warp's h slot (buf 0)

    float c = 0.f;                                    // identical in all lanes

    for (int s = 0; s < Tn; s++) {
        int t = dir ? (Tn - 1 - s) : s;

        // per-tile gate on GEMM progress (once per 128 steps)
        if ((s & 127) == 0) {
            if (tid == 0) {
                int mt = dir ? (15 - (s >> 7)) : (s >> 7);
                volatile int* f = &g_tflags[layer][dir][mt];
                while (*f < 8) { __nanosleep(200); }
                __threadfence();
            }
            __syncthreads();
        }

        float xgv = __ldg(&xg[(size_t)t * 1024 + xg_off]);

        float z = xgv;
        if (s > 0) {
            uint32_t want = (uint32_t)(s - 1);
            uint32_t b = pollb + ((s - 1) & 1) * (HDn * 8);
            unsigned long long p0, p1, p2, p3, p4, p5, p6, p7;
            int tries = 0;
            for (;;) {
                asm volatile("ld.volatile.shared.v2.u64 {%0,%1}, [%2];"
                             : "=l"(p0), "=l"(p1) : "r"(b));
                asm volatile("ld.volatile.shared.v2.u64 {%0,%1}, [%2];"
                             : "=l"(p2), "=l"(p3) : "r"(b + 512));
                asm volatile("ld.volatile.shared.v2.u64 {%0,%1}, [%2];"
                             : "=l"(p4), "=l"(p5) : "r"(b + 1024));
                asm volatile("ld.volatile.shared.v2.u64 {%0,%1}, [%2];"
                             : "=l"(p6), "=l"(p7) : "r"(b + 1536));
                bool ok = ((uint32_t)(p0 >> 32) == want) & ((uint32_t)(p1 >> 32) == want) &
                          ((uint32_t)(p2 >> 32) == want) & ((uint32_t)(p3 >> 32) == want) &
                          ((uint32_t)(p4 >> 32) == want) & ((uint32_t)(p5 >> 32) == want) &
                          ((uint32_t)(p6 >> 32) == want) & ((uint32_t)(p7 >> 32) == want);
                if (__all_sync(0xffffffffu, ok)) break;
                // adaptive backoff: two fast retries, then sleep (crossbar relief)
                if (++tries > 2) __nanosleep(20);
            }
            // pack h pairs (adjacent columns 2l, 2l+1 within each group)
            unsigned long long hx[4];
            hx[0] = pk2u((uint32_t)p0, (uint32_t)p1);
            hx[1] = pk2u((uint32_t)p2, (uint32_t)p3);
            hx[2] = pk2u((uint32_t)p4, (uint32_t)p5);
            hx[3] = pk2u((uint32_t)p6, (uint32_t)p7);

            float srow[4];
#pragma unroll
            for (int g = 0; g < 4; g++) {
                unsigned long long a = 0ull;
                fma2(a, wregs[g][0], hx[0]);
                fma2(a, wregs[g][1], hx[1]);
                fma2(a, wregs[g][2], hx[2]);
                fma2(a, wregs[g][3], hx[3]);
                float lo = __uint_as_float((uint32_t)a);
                float hi = __uint_as_float((uint32_t)(a >> 32));
                srow[g] = lo + hi;
            }
            // split-butterfly: 6 shfl; gate g lands in lane group 8g
#pragma unroll
            for (int i = 0; i < 2; i++) {
                float send = (lane & 16) ? srow[i] : srow[i + 2];
                float recv = __shfl_xor_sync(0xffffffffu, send, 16);
                srow[i] = ((lane & 16) ? srow[i + 2] : srow[i]) + recv;
            }
            {
                float send = (lane & 8) ? srow[0] : srow[1];
                float recv = __shfl_xor_sync(0xffffffffu, send, 8);
                srow[0] = ((lane & 8) ? srow[1] : srow[0]) + recv;
            }
            srow[0] += __shfl_xor_sync(0xffffffffu, srow[0], 4);
            srow[0] += __shfl_xor_sync(0xffffffffu, srow[0], 2);
            srow[0] += __shfl_xor_sync(0xffffffffu, srow[0], 1);
            z += srow[0];
        }

        // collect the 4 gates (all lanes receive; all maintain c identically)
        float zi = __shfl_sync(0xffffffffu, z, 0);
        float zf = __shfl_sync(0xffffffffu, z, 8);
        float zg = __shfl_sync(0xffffffffu, z, 16);
        float zo = __shfl_sync(0xffffffffu, z, 24);

        float ig = sig_apx(zi);
        float fg = sig_apx(zf);
        float og = sig_apx(zo);
        c = fg * c + ig * tanh_apx(zg);
        float h = og * tanh_apx(c);

        // publish: lanes 0..15 store (h | s<<32) to each cluster CTA;
        // the self-targeted store takes the cheap local path
        unsigned long long pv = pk2u(__float_as_uint(h), (uint32_t)s);
        uint32_t dst = dstoff + (s & 1) * (HDn * 8);
        if (lane < CSIZE) {
            if (lane == (int)rank) st_local_u64(dst, pv);
            else                   st_cluster_u64(dst, (uint32_t)lane, pv);
        }
        if (lane == 16)
            xnext[(size_t)t * Hn + dir * HDn + mycell] = h;
    }

    asm volatile("barrier.cluster.arrive.aligned;" ::: "memory");
    asm volatile("barrier.cluster.wait.aligned;" ::: "memory");
}

// ---------------- projection: feats = x2 @ W_out^T + b_out ----------------
__global__ void proj_kernel(const float* __restrict__ Wout,
                            const float* __restrict__ bout) {
    int t = blockIdx.x;
    __shared__ float xs[Hn];
    int tid = threadIdx.x;   // 160
    for (int i = tid; i < Hn; i += 160) xs[i] = g_x2[(long)t * Hn + i];
    __syncthreads();
    int tag = tid >> 3;      // 0..19
    int p = tid & 7;
    float sum = 0.f;
    const float* wr = Wout + (long)tag * Hn + p * 64;
    const float* xr = xs + p * 64;
#pragma unroll
    for (int i = 0; i < 64; i++) sum = fmaf(__ldg(&wr[i]), xr[i], sum);
    sum += __shfl_xor_sync(0xffffffffu, sum, 1);
    sum += __shfl_xor_sync(0xffffffffu, sum, 2);
    sum += __shfl_xor_sync(0xffffffffu, sum, 4);
    if (p == 0) g_feats[t * NTAGS + tag] = sum + __ldg(&bout[tag]);
}

// ---------------- Viterbi: one warp; feats preloaded into smem; tree argmax ---
#define VSMEM_BYTES (Tn * NTAGS * 4 + Tn * NTAGS)
__global__ void viterbi_kernel(const float* __restrict__ trans,
                               float* __restrict__ out, int out_size) {
    extern __shared__ unsigned char vsm[];
    float* fs = (float*)vsm;                          // [Tn][NTAGS]
    unsigned char* bp = vsm + Tn * NTAGS * 4;         // [Tn][NTAGS]

    int n = threadIdx.x;                              // 0..31
    for (int i = n; i < Tn * NTAGS; i += 32) fs[i] = __ldg(&g_feats[i]);

    bool act = (n < NTAGS);
    float tr[NTAGS];
#pragma unroll
    for (int p = 0; p < NTAGS; p++) tr[p] = act ? __ldg(&trans[n * NTAGS + p]) : 0.f;
    float trE = act ? __ldg(&trans[ENDT * NTAGS + n]) : 0.f;
    float v = act ? ((n == STARTT) ? 0.f : NEGV) : -1e30f;
    __syncwarp();

    for (int t = 0; t < Tn; t++) {
        float sc[NTAGS];
#pragma unroll
        for (int p = 0; p < NTAGS; p++)
            sc[p] = __shfl_sync(0xffffffffu, v, p) + tr[p];

        float mv[10]; int mi_[10];
#pragma unroll
        for (int i = 0; i < 10; i++) {
            bool left = sc[2 * i] >= sc[2 * i + 1];
            mv[i] = left ? sc[2 * i] : sc[2 * i + 1];
            mi_[i] = left ? 2 * i : 2 * i + 1;
        }
#pragma unroll
        for (int i = 0; i < 5; i++) {
            bool left = mv[2 * i] >= mv[2 * i + 1];
            mv[i] = left ? mv[2 * i] : mv[2 * i + 1];
            mi_[i] = left ? mi_[2 * i] : mi_[2 * i + 1];
        }
        {
            bool l0 = mv[0] >= mv[1];
            float v0 = l0 ? mv[0] : mv[1]; int i0 = l0 ? mi_[0] : mi_[1];
            bool l1 = mv[2] >= mv[3];
            float v1 = l1 ? mv[2] : mv[3]; int i1 = l1 ? mi_[2] : mi_[3];
            bool l2 = v0 >= v1;
            float v2 = l2 ? v0 : v1; int i2 = l2 ? i0 : i1;
            bool l3 = v2 >= mv[4];
            mv[0] = l3 ? v2 : mv[4]; mi_[0] = l3 ? i2 : mi_[4];
        }
        float feat = act ? fs[t * NTAGS + n] : 0.f;
        v = mv[0] + feat;
        if (act) bp[t * NTAGS + n] = (unsigned char)mi_[0];
    }

    float term = act ? (v + trE) : -1e30f;
    int idx = act ? n : 31;
#pragma unroll
    for (int off = 16; off; off >>= 1) {
        float ov = __shfl_xor_sync(0xffffffffu, term, off);
        int oi = __shfl_xor_sync(0xffffffffu, idx, off);
        if (ov > term || (ov == term && oi < idx)) { term = ov; idx = oi; }
    }
    __syncwarp();

    if (n == 0) {
        if (out_size > 0) out[0] = term;
        int tag = idx;
        for (int t = Tn - 1; t >= 0; t--) {
            if (1 + t < out_size) out[1 + t] = (float)tag;
            tag = bp[t * NTAGS + tag];
        }
        for (int i = Tn + 1; i < out_size; i++) out[i] = 0.f;
    }
}

// ---------------- launch ----------------
extern "C" void kernel_launch(void* const* d_in, const int* in_sizes, int n_in,
                              void* d_out, int out_size) {
    const int*   sent    = (const int*)d_in[0];
    const float* emb     = (const float*)d_in[1];
    const float* l0f_Wih = (const float*)d_in[2];
    const float* l0f_Whh = (const float*)d_in[3];
    const float* l0f_bih = (const float*)d_in[4];
    const float* l0f_bhh = (const float*)d_in[5];
    const float* l0b_Wih = (const float*)d_in[6];
    const float* l0b_Whh = (const float*)d_in[7];
    const float* l0b_bih = (const float*)d_in[8];
    const float* l0b_bhh = (const float*)d_in[9];
    const float* l1f_Wih = (const float*)d_in[10];
    const float* l1f_Whh = (const float*)d_in[11];
    const float* l1f_bih = (const float*)d_in[12];
    const float* l1f_bhh = (const float*)d_in[13];
    const float* l1b_Wih = (const float*)d_in[14];
    const float* l1b_Whh = (const float*)d_in[15];
    const float* l1b_bih = (const float*)d_in[16];
    const float* l1b_bhh = (const float*)d_in[17];
    const float* W_out   = (const float*)d_in[18];
    const float* b_out   = (const float*)d_in[19];
    const float* trans   = (const float*)d_in[20];
    float* out = (float*)d_out;

    static float* s_x1 = nullptr;
    static float* s_x2 = nullptr;
    static cudaStream_t s1 = nullptr;
    static cudaEvent_t ev0 = nullptr, ev1 = nullptr, ev2 = nullptr;
    if (!s_x1) {
        cudaGetSymbolAddress((void**)&s_x1, g_x1);
        cudaGetSymbolAddress((void**)&s_x2, g_x2);
        cudaStreamCreateWithFlags(&s1, cudaStreamNonBlocking);
        cudaEventCreateWithFlags(&ev0, cudaEventDisableTiming);
        cudaEventCreateWithFlags(&ev1, cudaEventDisableTiming);
        cudaEventCreateWithFlags(&ev2, cudaEventDisableTiming);
        cudaFuncSetAttribute(viterbi_kernel,
                             cudaFuncAttributeMaxDynamicSharedMemorySize, VSMEM_BYTES);
        cudaFuncSetAttribute(recur_kernel,
                             cudaFuncAttributeNonPortableClusterSizeAllowed, 1);
    }

    dim3 ggrid(8, 2, 16);   // n-tile, dir, mi (interleaved m-tiles)

    // stream 0 (captured): zero flags, then recurrences
    zero_flags_kernel<<<1, 64>>>();
    cudaEventRecord(ev0, 0);
    cudaStreamWaitEvent(s1, ev0, 0);

    // GEMM0 on side stream, concurrent with recur0 (flag-gated per tile)
    gemm_kernel<<<ggrid, 256, 0, s1>>>(0, nullptr, sent, emb, l0f_Wih, l0b_Wih,
                                       l0f_bih, l0f_bhh, l0b_bih, l0b_bhh);
    recur_kernel<<<2 * CSIZE, RTHREADS>>>(0, l0f_Whh, l0b_Whh, s_x1);

    // GEMM1 must wait for x1 (recur0 done), then runs concurrent with recur1
    cudaEventRecord(ev1, 0);
    cudaStreamWaitEvent(s1, ev1, 0);
    gemm_kernel<<<ggrid, 256, 0, s1>>>(1, s_x1, nullptr, nullptr, l1f_Wih, l1b_Wih,
                                       l1f_bih, l1f_bhh, l1b_bih, l1b_bhh);
    cudaEventRecord(ev2, s1);

    recur_kernel<<<2 * CSIZE, RTHREADS>>>(1, l1f_Whh, l1b_Whh, s_x2);

    // join side stream back before epilogue
    cudaStreamWaitEvent(0, ev2, 0);
    proj_kernel<<<Tn, 160>>>(W_out, b_out);
    viterbi_kernel<<<1, 32, VSMEM_BYTES>>>(trans, out, out_size);
}

// round 16
// speedup vs baseline: 1.1271x; 1.0974x over previous
#include <cuda_runtime.h>
#include <cstdint>

#define Tn     2048
#define Dn     512
#define Hn     512
#define HDn    256
#define NTAGS  20
#define STARTT 18
#define ENDT   19
#define NEGV   (-10000.0f)

#define CSIZE    16    // CTAs per direction (one nonportable cluster)
#define RTHREADS 512

// ---------------- scratch (static device memory; no allocations) ----------------
__device__ __align__(16) float g_xg[2][Tn * 1024];     // per-dir gate preactivations
__device__ __align__(16) float g_x1[Tn * Hn];          // layer0 output (concat f|b)
__device__ __align__(16) float g_x2[Tn * Hn];          // layer1 output
__device__ __align__(16) float g_feats[Tn * NTAGS];
__device__ int g_tflags[2][2][16];                     // [layer][dir][mtile] n-block arrivals

// ---------------- PTX helpers ----------------
__device__ __forceinline__ uint32_t smem_u32(const void* p) {
    return (uint32_t)__cvta_generic_to_shared(p);
}

// remote (cluster) 8-byte store: value+tag in one word, no fence needed
__device__ __forceinline__ void st_cluster_u64(uint32_t laddr, uint32_t rank,
                                               unsigned long long v) {
    asm volatile("{\n\t"
        ".reg .b32 ra;\n\t"
        "mapa.shared::cluster.u32 ra, %0, %1;\n\t"
        "st.shared::cluster.u64 [ra], %2;\n\t"
        "}" :: "r"(laddr), "r"(rank), "l"(v) : "memory");
}

__device__ __forceinline__ void fma2(unsigned long long& acc,
                                     unsigned long long a, unsigned long long b) {
    asm("fma.rn.f32x2 %0, %1, %2, %0;" : "+l"(acc) : "l"(a), "l"(b));
}

__device__ __forceinline__ unsigned long long pk2(float lo, float hi) {
    unsigned long long r;
    asm("mov.b64 %0, {%1, %2};" : "=l"(r) : "f"(lo), "f"(hi));
    return r;
}

__device__ __forceinline__ unsigned long long pk2u(uint32_t lo, uint32_t hi) {
    unsigned long long r;
    asm("mov.b64 %0, {%1, %2};" : "=l"(r) : "r"(lo), "r"(hi));
    return r;
}

// single-instruction MUFU.TANH (sm_75+); sigmoid via tanh identity
__device__ __forceinline__ float tanh_apx(float x) {
    float r;
    asm("tanh.approx.f32 %0, %1;" : "=f"(r) : "f"(x));
    return r;
}

__global__ void zero_flags_kernel() {
    int* p = &g_tflags[0][0][0];
    if (threadIdx.x < 64) p[threadIdx.x] = 0;
}

// ---------------- GEMM: XG[dir] = X @ W^T + (bih + bhh), with tile flags ------
__global__ __launch_bounds__(256)
void gemm_kernel(int layer,
                 const float* __restrict__ A,
                 const int* __restrict__ sent, const float* __restrict__ emb,
                 const float* __restrict__ W0, const float* __restrict__ W1,
                 const float* __restrict__ bi0, const float* __restrict__ bh0,
                 const float* __restrict__ bi1, const float* __restrict__ bh1) {
    const int K = 512;
    int dir = blockIdx.y;
    int mi = blockIdx.z;
    int mt = (mi & 1) ? (15 - (mi >> 1)) : (mi >> 1);
    const float* B  = dir ? W1 : W0;
    const float* bi = dir ? bi1 : bi0;
    const float* bh = dir ? bh1 : bh0;
    float* C = g_xg[dir];

    __shared__ float As[8][128];
    __shared__ float Bs[8][128];

    int tid = threadIdx.x;
    int bm = mt * 128;
    int bn = blockIdx.x * 128;
    int lr = tid >> 1;
    int lc = (tid & 1) * 4;
    int tx = tid & 15;
    int ty = tid >> 4;

    unsigned long long acc[8][4];
#pragma unroll
    for (int i = 0; i < 8; i++)
#pragma unroll
        for (int j = 0; j < 4; j++) acc[i][j] = 0ull;

    long arow = bm + lr;
    const float* Asrc = A;
    if (sent) { arow = __ldg(&sent[bm + lr]); Asrc = emb; }
    const float* Ap = Asrc + arow * K + lc;
    const float* Bp = B + (long)(bn + lr) * K + lc;

    for (int k0 = 0; k0 < K; k0 += 8) {
        float4 av = *(const float4*)(Ap + k0);
        float4 bv = *(const float4*)(Bp + k0);
        As[lc + 0][lr] = av.x; As[lc + 1][lr] = av.y;
        As[lc + 2][lr] = av.z; As[lc + 3][lr] = av.w;
        Bs[lc + 0][lr] = bv.x; Bs[lc + 1][lr] = bv.y;
        Bs[lc + 2][lr] = bv.z; Bs[lc + 3][lr] = bv.w;
        __syncthreads();
#pragma unroll
        for (int kk = 0; kk < 8; kk++) {
            float4 a0 = *(const float4*)&As[kk][ty * 4];
            float4 a1 = *(const float4*)&As[kk][64 + ty * 4];
            float4 b0 = *(const float4*)&Bs[kk][tx * 4];
            float4 b1 = *(const float4*)&Bs[kk][64 + tx * 4];
            float a[8] = {a0.x, a0.y, a0.z, a0.w, a1.x, a1.y, a1.z, a1.w};
            unsigned long long pb[4];
            pb[0] = pk2(b0.x, b0.y); pb[1] = pk2(b0.z, b0.w);
            pb[2] = pk2(b1.x, b1.y); pb[3] = pk2(b1.z, b1.w);
#pragma unroll
            for (int i = 0; i < 8; i++) {
                unsigned long long pa = pk2(a[i], a[i]);
#pragma unroll
                for (int j = 0; j < 4; j++)
                    fma2(acc[i][j], pa, pb[j]);
            }
        }
        __syncthreads();
    }

#pragma unroll
    for (int i = 0; i < 8; i++) {
        int m = bm + ((i < 4) ? (ty * 4 + i) : (64 + ty * 4 + (i - 4)));
#pragma unroll
        for (int j = 0; j < 8; j++) {
            int n = bn + ((j < 4) ? (tx * 4 + j) : (64 + tx * 4 + (j - 4)));
            unsigned long long p = acc[i][j >> 1];
            float v = __uint_as_float((j & 1) ? (uint32_t)(p >> 32) : (uint32_t)p);
            C[(long)m * 1024 + n] = v + __ldg(&bi[n]) + __ldg(&bh[n]);
        }
    }

    // publish tile completion
    __threadfence();
    __syncthreads();
    if (tid == 0) atomicAdd(&g_tflags[layer][dir][mt], 1);
}

// ---------------- recurrence: cluster-of-16, tagged-data, backoff poll --------
// R12 protocol (proven best): h travels as (value, step-tag) u64 words; lane l
// consumes columns {64k+2l, 64k+2l+1} with coalesced v2.u64 polls + immediate
// 40ns backoff on miss. R16 tail: the butterfly leaves gate g's z in lane
// group 8g, so each group applies ITS OWN gate's activation first (one MUFU
// per lane, branchless select of tanh vs sigmoid-via-tanh) and the shuffles
// collect already-activated values — MUFU work off the serial chain.
// Values are bit-identical to R12's formulas.
__global__ __launch_bounds__(RTHREADS, 1) __cluster_dims__(CSIZE, 1, 1)
void recur_kernel(int layer,
                  const float* __restrict__ Whh_f,
                  const float* __restrict__ Whh_b,
                  float* __restrict__ xnext) {
    __shared__ __align__(16) unsigned long long pairs[2][HDn];  // (h bits | tag<<32)

    int dir = blockIdx.x / CSIZE;
    uint32_t rank;
    asm("mov.u32 %0, %%cluster_ctarank;" : "=r"(rank));
    int cbase = (int)rank * 16;

    int tid = threadIdx.x;
    int w = tid >> 5;                    // warp -> local cell index 0..15
    int lane = tid & 31;
    int mycell = cbase + w;

    // init tags to invalid, then cluster-wide sync before any remote store
    (&pairs[0][0])[tid] = 0xFFFFFFFF00000000ull;     // 512 entries, 512 threads
    __syncthreads();
    asm volatile("barrier.cluster.arrive.aligned;" ::: "memory");
    asm volatile("barrier.cluster.wait.aligned;" ::: "memory");

    const float* Whh = dir ? Whh_b : Whh_f;
    const float* xg = g_xg[dir];

    // register-resident weights for gate g, columns {64k+2*lane, 64k+2*lane+1}
    unsigned long long wregs[4][4];
#pragma unroll
    for (int g = 0; g < 4; g++) {
        int grow = g * HDn + mycell;
#pragma unroll
        for (int k = 0; k < 4; k++)
            wregs[g][k] = *(const unsigned long long*)
                (Whh + (size_t)grow * HDn + 64 * k + 2 * lane);
    }

    int mygate = lane >> 3;                           // gate this lane group reduces to
    size_t xg_off = (size_t)mygate * HDn + mycell;

    // branchless activation select for this lane's gate:
    // gate 2 (cell input) -> tanh(z); others -> sigmoid(z) = 0.5*tanh(z/2)+0.5
    float asc = (mygate == 2) ? 1.f : 0.5f;
    bool  istanh = (mygate == 2);

    uint32_t pbase = smem_u32(&pairs[0][0]);
    uint32_t pollb = pbase + lane * 16;               // + 512*k + pb*2048
    uint32_t dstoff = pbase + mycell * 8;             // this warp's h slot (buf 0)

    float c = 0.f;                                    // identical in all lanes

    for (int s = 0; s < Tn; s++) {
        int t = dir ? (Tn - 1 - s) : s;

        // per-tile gate on GEMM progress (once per 128 steps)
        if ((s & 127) == 0) {
            if (tid == 0) {
                int mt = dir ? (15 - (s >> 7)) : (s >> 7);
                volatile int* f = &g_tflags[layer][dir][mt];
                while (*f < 8) { __nanosleep(200); }
                __threadfence();
            }
            __syncthreads();
        }

        float xgv = __ldg(&xg[(size_t)t * 1024 + xg_off]);

        float z = xgv;
        if (s > 0) {
            uint32_t want = (uint32_t)(s - 1);
            uint32_t b = pollb + ((s - 1) & 1) * (HDn * 8);
            unsigned long long p0, p1, p2, p3, p4, p5, p6, p7;
            for (;;) {
                asm volatile("ld.volatile.shared.v2.u64 {%0,%1}, [%2];"
                             : "=l"(p0), "=l"(p1) : "r"(b));
                asm volatile("ld.volatile.shared.v2.u64 {%0,%1}, [%2];"
                             : "=l"(p2), "=l"(p3) : "r"(b + 512));
                asm volatile("ld.volatile.shared.v2.u64 {%0,%1}, [%2];"
                             : "=l"(p4), "=l"(p5) : "r"(b + 1024));
                asm volatile("ld.volatile.shared.v2.u64 {%0,%1}, [%2];"
                             : "=l"(p6), "=l"(p7) : "r"(b + 1536));
                bool ok = ((uint32_t)(p0 >> 32) == want) & ((uint32_t)(p1 >> 32) == want) &
                          ((uint32_t)(p2 >> 32) == want) & ((uint32_t)(p3 >> 32) == want) &
                          ((uint32_t)(p4 >> 32) == want) & ((uint32_t)(p5 >> 32) == want) &
                          ((uint32_t)(p6 >> 32) == want) & ((uint32_t)(p7 >> 32) == want);
                if (__all_sync(0xffffffffu, ok)) break;
                __nanosleep(40);   // immediate backoff: free the crossbar (R12 tuned)
            }
            // pack h pairs (adjacent columns 2l, 2l+1 within each group)
            unsigned long long hx[4];
            hx[0] = pk2u((uint32_t)p0, (uint32_t)p1);
            hx[1] = pk2u((uint32_t)p2, (uint32_t)p3);
            hx[2] = pk2u((uint32_t)p4, (uint32_t)p5);
            hx[3] = pk2u((uint32_t)p6, (uint32_t)p7);

            float srow[4];
#pragma unroll
            for (int g = 0; g < 4; g++) {
                unsigned long long a = 0ull;
                fma2(a, wregs[g][0], hx[0]);
                fma2(a, wregs[g][1], hx[1]);
                fma2(a, wregs[g][2], hx[2]);
                fma2(a, wregs[g][3], hx[3]);
                float lo = __uint_as_float((uint32_t)a);
                float hi = __uint_as_float((uint32_t)(a >> 32));
                srow[g] = lo + hi;
            }
            // split-butterfly: 6 shfl; gate g lands in lane group 8g
#pragma unroll
            for (int i = 0; i < 2; i++) {
                float send = (lane & 16) ? srow[i] : srow[i + 2];
                float recv = __shfl_xor_sync(0xffffffffu, send, 16);
                srow[i] = ((lane & 16) ? srow[i + 2] : srow[i]) + recv;
            }
            {
                float send = (lane & 8) ? srow[0] : srow[1];
                float recv = __shfl_xor_sync(0xffffffffu, send, 8);
                srow[0] = ((lane & 8) ? srow[1] : srow[0]) + recv;
            }
            srow[0] += __shfl_xor_sync(0xffffffffu, srow[0], 4);
            srow[0] += __shfl_xor_sync(0xffffffffu, srow[0], 2);
            srow[0] += __shfl_xor_sync(0xffffffffu, srow[0], 1);
            z += srow[0];
        }

        // per-group activation FIRST (1 MUFU/lane), then collect activated values
        float tv = tanh_apx(z * asc);
        float av = istanh ? tv : fmaf(0.5f, tv, 0.5f);
        float ig = __shfl_sync(0xffffffffu, av, 0);
        float fg = __shfl_sync(0xffffffffu, av, 8);
        float tg = __shfl_sync(0xffffffffu, av, 16);
        float og = __shfl_sync(0xffffffffu, av, 24);

        c = fg * c + ig * tg;
        float h = og * tanh_apx(c);

        // publish: lanes 0..15 each store (h | s<<32) to one cluster CTA
        unsigned long long pv = pk2u(__float_as_uint(h), (uint32_t)s);
        uint32_t dst = dstoff + (s & 1) * (HDn * 8);
        if (lane < CSIZE) st_cluster_u64(dst, (uint32_t)lane, pv);
        if (lane == 16)
            xnext[(size_t)t * Hn + dir * HDn + mycell] = h;
    }

    asm volatile("barrier.cluster.arrive.aligned;" ::: "memory");
    asm volatile("barrier.cluster.wait.aligned;" ::: "memory");
}

// ---------------- projection: feats = x2 @ W_out^T + b_out ----------------
__global__ void proj_kernel(const float* __restrict__ Wout,
                            const float* __restrict__ bout) {
    int t = blockIdx.x;
    __shared__ float xs[Hn];
    int tid = threadIdx.x;   // 160
    for (int i = tid; i < Hn; i += 160) xs[i] = g_x2[(long)t * Hn + i];
    __syncthreads();
    int tag = tid >> 3;      // 0..19
    int p = tid & 7;
    float sum = 0.f;
    const float* wr = Wout + (long)tag * Hn + p * 64;
    const float* xr = xs + p * 64;
#pragma unroll
    for (int i = 0; i < 64; i++) sum = fmaf(__ldg(&wr[i]), xr[i], sum);
    sum += __shfl_xor_sync(0xffffffffu, sum, 1);
    sum += __shfl_xor_sync(0xffffffffu, sum, 2);
    sum += __shfl_xor_sync(0xffffffffu, sum, 4);
    if (p == 0) g_feats[t * NTAGS + tag] = sum + __ldg(&bout[tag]);
}

// ---------------- Viterbi: one warp; feats preloaded into smem; tree argmax ---
#define VSMEM_BYTES (Tn * NTAGS * 4 + Tn * NTAGS)
__global__ void viterbi_kernel(const float* __restrict__ trans,
                               float* __restrict__ out, int out_size) {
    extern __shared__ unsigned char vsm[];
    float* fs = (float*)vsm;                          // [Tn][NTAGS]
    unsigned char* bp = vsm + Tn * NTAGS * 4;         // [Tn][NTAGS]

    int n = threadIdx.x;                              // 0..31
    for (int i = n; i < Tn * NTAGS; i += 32) fs[i] = __ldg(&g_feats[i]);

    bool act = (n < NTAGS);
    float tr[NTAGS];
#pragma unroll
    for (int p = 0; p < NTAGS; p++) tr[p] = act ? __ldg(&trans[n * NTAGS + p]) : 0.f;
    float trE = act ? __ldg(&trans[ENDT * NTAGS + n]) : 0.f;
    float v = act ? ((n == STARTT) ? 0.f : NEGV) : -1e30f;
    __syncwarp();

    for (int t = 0; t < Tn; t++) {
        float sc[NTAGS];
#pragma unroll
        for (int p = 0; p < NTAGS; p++)
            sc[p] = __shfl_sync(0xffffffffu, v, p) + tr[p];

        float mv[10]; int mi_[10];
#pragma unroll
        for (int i = 0; i < 10; i++) {
            bool left = sc[2 * i] >= sc[2 * i + 1];
            mv[i] = left ? sc[2 * i] : sc[2 * i + 1];
            mi_[i] = left ? 2 * i : 2 * i + 1;
        }
#pragma unroll
        for (int i = 0; i < 5; i++) {
            bool left = mv[2 * i] >= mv[2 * i + 1];
            mv[i] = left ? mv[2 * i] : mv[2 * i + 1];
            mi_[i] = left ? mi_[2 * i] : mi_[2 * i + 1];
        }
        {
            bool l0 = mv[0] >= mv[1];
            float v0 = l0 ? mv[0] : mv[1]; int i0 = l0 ? mi_[0] : mi_[1];
            bool l1 = mv[2] >= mv[3];
            float v1 = l1 ? mv[2] : mv[3]; int i1 = l1 ? mi_[2] : mi_[3];
            bool l2 = v0 >= v1;
            float v2 = l2 ? v0 : v1; int i2 = l2 ? i0 : i1;
            bool l3 = v2 >= mv[4];
            mv[0] = l3 ? v2 : mv[4]; mi_[0] = l3 ? i2 : mi_[4];
        }
        float feat = act ? fs[t * NTAGS + n] : 0.f;
        v = mv[0] + feat;
        if (act) bp[t * NTAGS + n] = (unsigned char)mi_[0];
    }

    float term = act ? (v + trE) : -1e30f;
    int idx = act ? n : 31;
#pragma unroll
    for (int off = 16; off; off >>= 1) {
        float ov = __shfl_xor_sync(0xffffffffu, term, off);
        int oi = __shfl_xor_sync(0xffffffffu, idx, off);
        if (ov > term || (ov == term && oi < idx)) { term = ov; idx = oi; }
    }
    __syncwarp();

    if (n == 0) {
        if (out_size > 0) out[0] = term;
        int tag = idx;
        for (int t = Tn - 1; t >= 0; t--) {
            if (1 + t < out_size) out[1 + t] = (float)tag;
            tag = bp[t * NTAGS + tag];
        }
        for (int i = Tn + 1; i < out_size; i++) out[i] = 0.f;
    }
}

// ---------------- launch ----------------
extern "C" void kernel_launch(void* const* d_in, const int* in_sizes, int n_in,
                              void* d_out, int out_size) {
    const int*   sent    = (const int*)d_in[0];
    const float* emb     = (const float*)d_in[1];
    const float* l0f_Wih = (const float*)d_in[2];
    const float* l0f_Whh = (const float*)d_in[3];
    const float* l0f_bih = (const float*)d_in[4];
    const float* l0f_bhh = (const float*)d_in[5];
    const float* l0b_Wih = (const float*)d_in[6];
    const float* l0b_Whh = (const float*)d_in[7];
    const float* l0b_bih = (const float*)d_in[8];
    const float* l0b_bhh = (const float*)d_in[9];
    const float* l1f_Wih = (const float*)d_in[10];
    const float* l1f_Whh = (const float*)d_in[11];
    const float* l1f_bih = (const float*)d_in[12];
    const float* l1f_bhh = (const float*)d_in[13];
    const float* l1b_Wih = (const float*)d_in[14];
    const float* l1b_Whh = (const float*)d_in[15];
    const float* l1b_bih = (const float*)d_in[16];
    const float* l1b_bhh = (const float*)d_in[17];
    const float* W_out   = (const float*)d_in[18];
    const float* b_out   = (const float*)d_in[19];
    const float* trans   = (const float*)d_in[20];
    float* out = (float*)d_out;

    static float* s_x1 = nullptr;
    static float* s_x2 = nullptr;
    static cudaStream_t s1 = nullptr;
    static cudaEvent_t ev0 = nullptr, ev1 = nullptr, ev2 = nullptr;
    if (!s_x1) {
        cudaGetSymbolAddress((void**)&s_x1, g_x1);
        cudaGetSymbolAddress((void**)&s_x2, g_x2);
        cudaStreamCreateWithFlags(&s1, cudaStreamNonBlocking);
        cudaEventCreateWithFlags(&ev0, cudaEventDisableTiming);
        cudaEventCreateWithFlags(&ev1, cudaEventDisableTiming);
        cudaEventCreateWithFlags(&ev2, cudaEventDisableTiming);
        cudaFuncSetAttribute(viterbi_kernel,
                             cudaFuncAttributeMaxDynamicSharedMemorySize, VSMEM_BYTES);
        cudaFuncSetAttribute(recur_kernel,
                             cudaFuncAttributeNonPortableClusterSizeAllowed, 1);
    }

    dim3 ggrid(8, 2, 16);   // n-tile, dir, mi (interleaved m-tiles)

    // stream 0 (captured): zero flags, then recurrences
    zero_flags_kernel<<<1, 64>>>();
    cudaEventRecord(ev0, 0);
    cudaStreamWaitEvent(s1, ev0, 0);

    // GEMM0 on side stream, concurrent with recur0 (flag-gated per tile)
    gemm_kernel<<<ggrid, 256, 0, s1>>>(0, nullptr, sent, emb, l0f_Wih, l0b_Wih,
                                       l0f_bih, l0f_bhh, l0b_bih, l0b_bhh);
    recur_kernel<<<2 * CSIZE, RTHREADS>>>(0, l0f_Whh, l0b_Whh, s_x1);

    // GEMM1 must wait for x1 (recur0 done), then runs concurrent with recur1
    cudaEventRecord(ev1, 0);
    cudaStreamWaitEvent(s1, ev1, 0);
    gemm_kernel<<<ggrid, 256, 0, s1>>>(1, s_x1, nullptr, nullptr, l1f_Wih, l1b_Wih,
                                       l1f_bih, l1f_bhh, l1b_bih, l1b_bhh);
    cudaEventRecord(ev2, s1);

    recur_kernel<<<2 * CSIZE, RTHREADS>>>(1, l1f_Whh, l1b_Whh, s_x2);

    // join side stream back before epilogue
    cudaStreamWaitEvent(0, ev2, 0);
    proj_kernel<<<Tn, 160>>>(W_out, b_out);
    viterbi_kernel<<<1, 32, VSMEM_BYTES>>>(trans, out, out_size);
}